// round 2
// baseline (speedup 1.0000x reference)
#include <cuda_runtime.h>
#include <cstdint>

#define B_ 2
#define H_ 8
#define S_ 1024
#define DK_ 64
#define DV_ 64
static constexpr float INV_T = 0.125f;              // 1/temperature (1/8)
static constexpr int OUT_ATTN_OFF = B_ * H_ * S_ * DV_;  // 1048576

// ---------------------------------------------------------------------------
// K1: attn1[b,h,i,j] = (q/T)[b,h,i,:] . k[b,h,j,:]
// Batched SGEMM: 16 batches of [1024 x 1024 x 64]. 64x64 CTA tile, 4x4 thread tile.
// Tiles staged transposed ([d][row]) so compute uses conflict-free float4 LDS.
// ---------------------------------------------------------------------------
__global__ void __launch_bounds__(256) k1_qk(const float* __restrict__ q,
                                             const float* __restrict__ k,
                                             float* __restrict__ attn)
{
    __shared__ float Qt[64][68];  // Qt[d][i]
    __shared__ float Kt[64][68];  // Kt[d][j]
    const int bh = blockIdx.z;
    const int i0 = blockIdx.y * 64;
    const int j0 = blockIdx.x * 64;
    const float* qb = q + ((size_t)bh * S_ + i0) * DK_;
    const float* kb = k + ((size_t)bh * S_ + j0) * DK_;
    const int t = threadIdx.x;

    // stage (transpose): 64 rows x 16 float4
    #pragma unroll
    for (int idx = t; idx < 64 * 16; idx += 256) {
        const int row = idx >> 4;
        const int d4  = (idx & 15) << 2;
        float4 a = *(const float4*)(qb + (size_t)row * DK_ + d4);
        Qt[d4 + 0][row] = a.x; Qt[d4 + 1][row] = a.y;
        Qt[d4 + 2][row] = a.z; Qt[d4 + 3][row] = a.w;
        float4 b = *(const float4*)(kb + (size_t)row * DK_ + d4);
        Kt[d4 + 0][row] = b.x; Kt[d4 + 1][row] = b.y;
        Kt[d4 + 2][row] = b.z; Kt[d4 + 3][row] = b.w;
    }
    __syncthreads();

    const int tx = t & 15, ty = t >> 4;
    float acc[4][4] = {};
    #pragma unroll 16
    for (int d = 0; d < 64; d++) {
        float4 a = *(const float4*)&Qt[d][ty * 4];
        float4 b = *(const float4*)&Kt[d][tx * 4];
        float av[4] = {a.x, a.y, a.z, a.w};
        float bv[4] = {b.x, b.y, b.z, b.w};
        #pragma unroll
        for (int u = 0; u < 4; u++)
            #pragma unroll
            for (int vv = 0; vv < 4; vv++)
                acc[u][vv] = fmaf(av[u], bv[vv], acc[u][vv]);
    }

    float* ab = attn + (((size_t)bh * S_ + i0) * S_) + j0;
    #pragma unroll
    for (int u = 0; u < 4; u++) {
        float4 o = make_float4(acc[u][0] * INV_T, acc[u][1] * INV_T,
                               acc[u][2] * INV_T, acc[u][3] * INV_T);
        *(float4*)(ab + (size_t)(ty * 4 + u) * S_ + tx * 4) = o;
    }
}

// ---------------------------------------------------------------------------
// K2: per (b, i):  logits[h][j] = attn1[h][j] + qs[h,:] . rpr[b,i,j,:]
//     then mask, softmax over j, write final attn probabilities.
// rpr (512 MB total) is streamed exactly once; all 8 heads share each rpr row.
// Dynamic smem: qs (packed for f32x2-friendly loads) + logits[8][1024] + rpr chunk.
// ---------------------------------------------------------------------------
static constexpr int K2_CHUNK = 256;
static constexpr int K2_RS_PITCH = 66;  // conflict-free for float2 loads (bank stride 2)
static constexpr int K2_SMEM_QS = 4 * 64 * 2 * 4;                 // 2048 B
static constexpr int K2_SMEM_LOGIT = 8 * 1024 * 4;                // 32768 B
static constexpr int K2_SMEM_RS = K2_CHUNK * K2_RS_PITCH * 4;     // 67584 B
static constexpr int K2_SMEM_TOTAL = K2_SMEM_QS + K2_SMEM_LOGIT + K2_SMEM_RS;  // 102400 B

__global__ void __launch_bounds__(256) k2_rpr_softmax(
    const float* __restrict__ q,
    const float* __restrict__ rpr,
    const int* __restrict__ mask,
    float* __restrict__ attn)   // in: attn1 logits, out: softmax probs (in place)
{
    extern __shared__ char smem_raw[];
    float* qs    = (float*)smem_raw;                       // [4][64][2]: (hpair, d, h-in-pair)
    float* logit = (float*)(smem_raw + K2_SMEM_QS);        // [8][1024]
    float* rs    = (float*)(smem_raw + K2_SMEM_QS + K2_SMEM_LOGIT);  // [256][66]

    const int b = blockIdx.y;
    const int i = blockIdx.x;
    const int t = threadIdx.x;

    // load q row for all 8 heads, scaled; layout qs[hp][d][c] = q[h=2hp+c][d]/T
    #pragma unroll
    for (int idx = t; idx < 512; idx += 256) {
        const int h = idx >> 6, d = idx & 63;
        qs[(((h >> 1) * 64) + d) * 2 + (h & 1)] =
            q[(((size_t)b * H_ + h) * S_ + i) * DK_ + d] * INV_T;
    }

    const int jt = t & 63;
    const int hp = t >> 6;                // 0..3
    const int h0 = hp * 2, h1 = h0 + 1;
    const float* rbase = rpr + ((size_t)b * S_ + i) * S_ * DK_;
    const float* a0 = attn + (((size_t)b * H_ + h0) * S_ + i) * S_;
    const float* a1 = attn + (((size_t)b * H_ + h1) * S_ + i) * S_;
    const int* mrow = mask + ((size_t)b * S_ + i) * S_;
    const float* qrow = qs + hp * 128;    // [64][2] for this head pair

    for (int jc = 0; jc < S_; jc += K2_CHUNK) {
        // stage rpr chunk [256][64] -> rs with pitch 66
        const float4* src = (const float4*)(rbase + (size_t)jc * DK_);
        #pragma unroll
        for (int idx = t; idx < K2_CHUNK * 16; idx += 256) {
            const int jj = idx >> 4;
            const int d4 = (idx & 15) << 2;
            float4 vv = src[idx];
            float* r = rs + jj * K2_RS_PITCH + d4;
            r[0] = vv.x; r[1] = vv.y; r[2] = vv.z; r[3] = vv.w;
        }
        __syncthreads();

        float acc[2][4] = {};
        #pragma unroll 8
        for (int d = 0; d < 64; d += 2) {
            // qv = (q[h0][d], q[h1][d], q[h0][d+1], q[h1][d+1]) broadcast to warp
            float4 qv = *(const float4*)(qrow + d * 2);
            #pragma unroll
            for (int m = 0; m < 4; m++) {
                float2 r = *(const float2*)(rs + (jt + 64 * m) * K2_RS_PITCH + d);
                acc[0][m] = fmaf(qv.x, r.x, acc[0][m]);
                acc[1][m] = fmaf(qv.y, r.x, acc[1][m]);
                acc[0][m] = fmaf(qv.z, r.y, acc[0][m]);
                acc[1][m] = fmaf(qv.w, r.y, acc[1][m]);
            }
        }

        #pragma unroll
        for (int m = 0; m < 4; m++) {
            const int j = jc + jt + 64 * m;
            const int mk = mrow[j];
            const float l0 = mk ? (acc[0][m] + a0[j]) : -1e9f;
            const float l1 = mk ? (acc[1][m] + a1[j]) : -1e9f;
            logit[h0 * 1024 + j] = l0;
            logit[h1 * 1024 + j] = l1;
        }
        __syncthreads();
    }

    // softmax: warp w handles head w (8 warps exactly)
    const int w = t >> 5, lane = t & 31;
    const float* lrow = logit + w * 1024;
    float vals[32];
    float mx = -3.4e38f;
    #pragma unroll
    for (int m = 0; m < 32; m++) {
        vals[m] = lrow[lane + 32 * m];
        mx = fmaxf(mx, vals[m]);
    }
    #pragma unroll
    for (int o = 16; o > 0; o >>= 1) mx = fmaxf(mx, __shfl_xor_sync(0xffffffffu, mx, o));
    float sum = 0.f;
    #pragma unroll
    for (int m = 0; m < 32; m++) { vals[m] = __expf(vals[m] - mx); sum += vals[m]; }
    #pragma unroll
    for (int o = 16; o > 0; o >>= 1) sum += __shfl_xor_sync(0xffffffffu, sum, o);
    const float rinv = 1.0f / sum;

    float* arow = attn + (((size_t)b * H_ + w) * S_ + i) * S_;
    #pragma unroll
    for (int m = 0; m < 32; m++) arow[lane + 32 * m] = vals[m] * rinv;
}

// ---------------------------------------------------------------------------
// K3: output[b,h,i,:] = sum_j attn[b,h,i,j] * v[b,h,j,:]
// Batched GEMM [1024 x 64 x 1024] per (b,h). 64-row i-tiles, j-chunked by 64.
// attn tile staged transposed ([j][i]); v tile staged straight ([j][n]).
// ---------------------------------------------------------------------------
__global__ void __launch_bounds__(256) k3_av(const float* __restrict__ attn,
                                             const float* __restrict__ v,
                                             float* __restrict__ out)
{
    __shared__ float At[64][68];  // At[j][i]
    __shared__ float Vs[64][68];  // Vs[j][n]
    const int bh = blockIdx.y;
    const int i0 = blockIdx.x * 64;
    const int t = threadIdx.x;
    const int tx = t & 15, ty = t >> 4;
    const float* ab = attn + ((size_t)bh * S_ + i0) * S_;
    const float* vb = v + (size_t)bh * S_ * DV_;

    float acc[4][4] = {};
    for (int jc = 0; jc < S_; jc += 64) {
        #pragma unroll
        for (int idx = t; idx < 64 * 16; idx += 256) {
            const int row = idx >> 4;
            const int d4  = (idx & 15) << 2;
            float4 a = *(const float4*)(ab + (size_t)row * S_ + jc + d4);
            At[d4 + 0][row] = a.x; At[d4 + 1][row] = a.y;
            At[d4 + 2][row] = a.z; At[d4 + 3][row] = a.w;
            float4 vv = *(const float4*)(vb + (size_t)(jc + row) * DV_ + d4);
            *(float4*)&Vs[row][d4] = vv;
        }
        __syncthreads();
        #pragma unroll 16
        for (int j = 0; j < 64; j++) {
            float4 a = *(const float4*)&At[j][ty * 4];
            float4 b = *(const float4*)&Vs[j][tx * 4];
            float av[4] = {a.x, a.y, a.z, a.w};
            float bv[4] = {b.x, b.y, b.z, b.w};
            #pragma unroll
            for (int u = 0; u < 4; u++)
                #pragma unroll
                for (int vv2 = 0; vv2 < 4; vv2++)
                    acc[u][vv2] = fmaf(av[u], bv[vv2], acc[u][vv2]);
        }
        __syncthreads();
    }

    float* ob = out + ((size_t)bh * S_ + i0) * DV_;
    #pragma unroll
    for (int u = 0; u < 4; u++) {
        float4 o = make_float4(acc[u][0], acc[u][1], acc[u][2], acc[u][3]);
        *(float4*)(ob + (size_t)(ty * 4 + u) * DV_ + tx * 4) = o;
    }
}

// ---------------------------------------------------------------------------
extern "C" void kernel_launch(void* const* d_in, const int* in_sizes, int n_in,
                              void* d_out, int out_size)
{
    const float* q    = (const float*)d_in[0];
    const float* k    = (const float*)d_in[1];
    const float* v    = (const float*)d_in[2];
    const int*   mask = (const int*)d_in[3];
    const float* rpr  = (const float*)d_in[4];
    float* out  = (float*)d_out;
    float* attn = out + OUT_ATTN_OFF;

    // K2 needs >48KB dynamic smem; setting the attribute is not a stream op
    // and is safe under graph capture.
    cudaFuncSetAttribute(k2_rpr_softmax,
                         cudaFuncAttributeMaxDynamicSharedMemorySize,
                         K2_SMEM_TOTAL);

    // K1: attn1 logits into the attn region of d_out (scratch, overwritten in K2)
    {
        dim3 grid(S_ / 64, S_ / 64, B_ * H_);
        k1_qk<<<grid, 256>>>(q, k, attn);
    }
    // K2: + positional term, mask, softmax (in place on attn region)
    {
        dim3 grid(S_, B_);
        k2_rpr_softmax<<<grid, 256, K2_SMEM_TOTAL>>>(q, rpr, mask, attn);
    }
    // K3: output = attn @ v
    {
        dim3 grid(S_ / 64, B_ * H_);
        k3_av<<<grid, 256>>>(attn, v, out);
    }
}

// round 3
// speedup vs baseline: 1.1257x; 1.1257x over previous
#include <cuda_runtime.h>
#include <cstdint>

#define B_ 2
#define H_ 8
#define S_ 1024
#define DK_ 64
#define DV_ 64
static constexpr float INV_T = 0.125f;                   // 1/temperature
static constexpr int OUT_ATTN_OFF = B_ * H_ * S_ * DV_;  // 1048576

// ---- packed fp32 helpers (sm_103a f32x2 pipe) -------------------------------
#define FMA2(acc, a, b) asm("fma.rn.f32x2 %0, %1, %2, %0;" : "+l"(acc) : "l"(a), "l"(b))

__device__ __forceinline__ unsigned long long dup2(float x) {
    unsigned long long r;
    asm("mov.b64 %0, {%1, %1};" : "=l"(r) : "f"(x));
    return r;
}
__device__ __forceinline__ float2 unpack2(unsigned long long v) {
    float2 r;
    asm("mov.b64 {%0, %1}, %2;" : "=f"(r.x), "=f"(r.y) : "l"(v));
    return r;
}

// ---------------------------------------------------------------------------
// K1: attn1[b,h,i,j] = (q/T)[b,h,i,:] . k[b,h,j,:]
// 128x128 CTA tile, 8x8 per-thread micro-tile, packed f32x2 accumulators
// (pairs of i-rows). Tiles staged transposed [d][row] with conflict-free STS.
// ---------------------------------------------------------------------------
static constexpr int K1_PITCH = 132;
static constexpr int K1_SMEM = 2 * 64 * K1_PITCH * 4;  // 67584 B

__global__ void __launch_bounds__(256) k1_qk(const float* __restrict__ q,
                                             const float* __restrict__ k,
                                             float* __restrict__ attn)
{
    extern __shared__ float sm1[];
    float* Qt = sm1;                   // [64][132]  Qt[d][i], pre-scaled by 1/T
    float* Kt = sm1 + 64 * K1_PITCH;   // [64][132]  Kt[d][j]

    const int bh = blockIdx.z;
    const int i0 = blockIdx.y * 128;
    const int j0 = blockIdx.x * 128;
    const float* qb = q + ((size_t)bh * S_ + i0) * DK_;
    const float* kb = k + ((size_t)bh * S_ + j0) * DK_;
    const int t = threadIdx.x;

    // stage + transpose; row = low bits => within-warp rows distinct mod 32
    // => STS.32 conflict-free. Global reads 16B/row at 256B stride (L2-hot).
    #pragma unroll
    for (int idx = t; idx < 2048; idx += 256) {
        const int row = idx & 127;
        const int d4  = ((idx >> 7) & 15) << 2;
        float4 a = *(const float4*)(qb + (size_t)row * DK_ + d4);
        Qt[(d4 + 0) * K1_PITCH + row] = a.x * INV_T;
        Qt[(d4 + 1) * K1_PITCH + row] = a.y * INV_T;
        Qt[(d4 + 2) * K1_PITCH + row] = a.z * INV_T;
        Qt[(d4 + 3) * K1_PITCH + row] = a.w * INV_T;
        float4 b = *(const float4*)(kb + (size_t)row * DK_ + d4);
        Kt[(d4 + 0) * K1_PITCH + row] = b.x;
        Kt[(d4 + 1) * K1_PITCH + row] = b.y;
        Kt[(d4 + 2) * K1_PITCH + row] = b.z;
        Kt[(d4 + 3) * K1_PITCH + row] = b.w;
    }
    __syncthreads();

    const int tx = t & 15, ty = t >> 4;
    const float* qp = Qt + ty * 8;
    const float* kp = Kt + tx * 8;

    unsigned long long acc[4][8] = {};  // acc[p][v]: i-pair (2p,2p+1) x j (v)

    #pragma unroll 4
    for (int d = 0; d < 64; d++) {
        const float* qd = qp + d * K1_PITCH;
        const float* kd = kp + d * K1_PITCH;
        ulonglong2 a01 = *(const ulonglong2*)qd;        // (i0,i1),(i2,i3)
        ulonglong2 a23 = *(const ulonglong2*)(qd + 4);  // (i4,i5),(i6,i7)
        float4 b0 = *(const float4*)kd;
        float4 b1 = *(const float4*)(kd + 4);
        unsigned long long av[4] = {a01.x, a01.y, a23.x, a23.y};
        unsigned long long bb[8] = {dup2(b0.x), dup2(b0.y), dup2(b0.z), dup2(b0.w),
                                    dup2(b1.x), dup2(b1.y), dup2(b1.z), dup2(b1.w)};
        #pragma unroll
        for (int p = 0; p < 4; p++)
            #pragma unroll
            for (int v = 0; v < 8; v++)
                FMA2(acc[p][v], av[p], bb[v]);
    }

    float* ab = attn + (((size_t)bh * S_ + i0 + ty * 8) * S_) + j0 + tx * 8;
    #pragma unroll
    for (int p = 0; p < 4; p++) {
        float r0[8], r1[8];
        #pragma unroll
        for (int v = 0; v < 8; v++) {
            float2 pv = unpack2(acc[p][v]);
            r0[v] = pv.x; r1[v] = pv.y;
        }
        float* row0 = ab + (size_t)(2 * p) * S_;
        float* row1 = ab + (size_t)(2 * p + 1) * S_;
        *(float4*)(row0)     = make_float4(r0[0], r0[1], r0[2], r0[3]);
        *(float4*)(row0 + 4) = make_float4(r0[4], r0[5], r0[6], r0[7]);
        *(float4*)(row1)     = make_float4(r1[0], r1[1], r1[2], r1[3]);
        *(float4*)(row1 + 4) = make_float4(r1[4], r1[5], r1[6], r1[7]);
    }
}

// ---------------------------------------------------------------------------
// K2: per (b,i): logits[h][j] = attn1[h][j] + qs[h,:] . rpr[b,i,j,:]
//     mask, softmax over j, write final probs. rpr streamed exactly once.
// Each thread owns one j per 256-chunk and all 8 heads (4 packed head-pair
// accumulators) -> each staged rpr value read once from smem.
// ---------------------------------------------------------------------------
static constexpr int K2_CHUNK = 256;
static constexpr int K2_RS_PITCH = 66;
static constexpr int K2_SMEM_QS = 512 * 4;                        // 2048 B
static constexpr int K2_SMEM_LOGIT = 8 * 1024 * 4;                // 32768 B
static constexpr int K2_SMEM_RS = K2_CHUNK * K2_RS_PITCH * 4;     // 67584 B
static constexpr int K2_SMEM_TOTAL = K2_SMEM_QS + K2_SMEM_LOGIT + K2_SMEM_RS;  // 102400

__global__ void __launch_bounds__(256) k2_rpr_softmax(
    const float* __restrict__ q,
    const float* __restrict__ rpr,
    const int* __restrict__ mask,
    float* __restrict__ attn)
{
    extern __shared__ char smem_raw[];
    float* qs    = (float*)smem_raw;                               // [4][64][2]
    float* logit = (float*)(smem_raw + K2_SMEM_QS);                // [8][1024]
    float* rs    = (float*)(smem_raw + K2_SMEM_QS + K2_SMEM_LOGIT);// [256][66]

    const int b = blockIdx.y;
    const int i = blockIdx.x;
    const int t = threadIdx.x;

    // qs[hp][d][c] = q[h=2hp+c][d] / T   (adjacent floats = head pair = f32x2)
    #pragma unroll
    for (int idx = t; idx < 512; idx += 256) {
        const int h = idx >> 6, d = idx & 63;
        qs[(((h >> 1) * 64) + d) * 2 + (h & 1)] =
            q[(((size_t)b * H_ + h) * S_ + i) * DK_ + d] * INV_T;
    }

    const float* rbase = rpr + ((size_t)b * S_ + i) * S_ * DK_;
    const int* mrow = mask + ((size_t)b * S_ + i) * S_;

    for (int jc = 0; jc < S_; jc += K2_CHUNK) {
        __syncthreads();  // qs ready (1st iter) / rs consumers done (later)
        // stage rpr chunk [256][64] -> rs (pitch 66, STS.64 at wavefront floor)
        const float4* src = (const float4*)(rbase + (size_t)jc * DK_);
        #pragma unroll
        for (int idx = t; idx < K2_CHUNK * 16; idx += 256) {
            const int jj = idx >> 4;
            const int d4 = (idx & 15) << 2;
            float4 v4 = src[idx];
            float* r = rs + jj * K2_RS_PITCH + d4;
            *(float2*)(r)     = make_float2(v4.x, v4.y);
            *(float2*)(r + 2) = make_float2(v4.z, v4.w);
        }
        __syncthreads();

        unsigned long long acc[4] = {};  // head pairs (h0,h1) packed
        const float* rr = rs + t * K2_RS_PITCH;
        #pragma unroll 8
        for (int d = 0; d < 64; d += 2) {
            float2 r2 = *(const float2*)(rr + d);
            unsigned long long rx = dup2(r2.x);
            unsigned long long ry = dup2(r2.y);
            #pragma unroll
            for (int hp = 0; hp < 4; hp++) {
                ulonglong2 qq = *(const ulonglong2*)(qs + hp * 128 + d * 2);
                FMA2(acc[hp], qq.x, rx);
                FMA2(acc[hp], qq.y, ry);
            }
        }

        const int j = jc + t;
        const int mk = mrow[j];
        #pragma unroll
        for (int hp = 0; hp < 4; hp++) {
            float2 av = unpack2(acc[hp]);
            const float a0 = attn[(((size_t)b * H_ + 2 * hp)     * S_ + i) * S_ + j];
            const float a1 = attn[(((size_t)b * H_ + 2 * hp + 1) * S_ + i) * S_ + j];
            logit[(2 * hp)     * 1024 + j] = mk ? (av.x + a0) : -1e9f;
            logit[(2 * hp + 1) * 1024 + j] = mk ? (av.y + a1) : -1e9f;
        }
    }
    __syncthreads();

    // softmax: warp w handles head w
    const int w = t >> 5, lane = t & 31;
    const float* lrow = logit + w * 1024;
    float vals[32];
    float mx = -3.4e38f;
    #pragma unroll
    for (int m = 0; m < 32; m++) {
        vals[m] = lrow[lane + 32 * m];
        mx = fmaxf(mx, vals[m]);
    }
    #pragma unroll
    for (int o = 16; o > 0; o >>= 1) mx = fmaxf(mx, __shfl_xor_sync(0xffffffffu, mx, o));
    float sum = 0.f;
    #pragma unroll
    for (int m = 0; m < 32; m++) { vals[m] = __expf(vals[m] - mx); sum += vals[m]; }
    #pragma unroll
    for (int o = 16; o > 0; o >>= 1) sum += __shfl_xor_sync(0xffffffffu, sum, o);
    const float rinv = 1.0f / sum;

    float* arow = attn + (((size_t)b * H_ + w) * S_ + i) * S_;
    #pragma unroll
    for (int m = 0; m < 32; m++) arow[lane + 32 * m] = vals[m] * rinv;
}

// ---------------------------------------------------------------------------
// K3: output[b,h,i,:] = sum_j attn[b,h,i,j] * v[b,h,j,:]
// Broadcast-A design: no transpose anywhere. Warp w owns 8 i-rows, lane owns
// an n-pair (f32x2). A values are warp-uniform smem broadcasts.
// ---------------------------------------------------------------------------
__global__ void __launch_bounds__(256) k3_av(const float* __restrict__ attn,
                                             const float* __restrict__ v,
                                             float* __restrict__ out)
{
    __shared__ float As[64][64];  // As[i][j]  (natural layout)
    __shared__ float Vs[64][64];  // Vs[j][n]  (natural layout)
    const int bh = blockIdx.y;
    const int i0 = blockIdx.x * 64;
    const int t = threadIdx.x;
    const int w = t >> 5, l = t & 31;
    const float* ab = attn + ((size_t)bh * S_ + i0) * S_;
    const float* vb = v + (size_t)bh * S_ * DV_;

    unsigned long long acc[8] = {};  // 8 i-rows x n-pair(2l,2l+1)

    for (int jc = 0; jc < S_; jc += 64) {
        __syncthreads();
        #pragma unroll
        for (int idx = t; idx < 1024; idx += 256) {
            const int row = idx >> 4;
            const int d4  = (idx & 15) << 2;
            *(float4*)&As[row][d4] = *(const float4*)(ab + (size_t)row * S_ + jc + d4);
            *(float4*)&Vs[row][d4] = *(const float4*)(vb + (size_t)(jc + row) * DV_ + d4);
        }
        __syncthreads();

        #pragma unroll 4
        for (int j4 = 0; j4 < 64; j4 += 4) {
            unsigned long long vv[4];
            #pragma unroll
            for (int kk = 0; kk < 4; kk++)
                vv[kk] = *(const unsigned long long*)&Vs[j4 + kk][l * 2];
            #pragma unroll
            for (int r = 0; r < 8; r++) {
                float4 a4 = *(const float4*)&As[w * 8 + r][j4];  // broadcast
                FMA2(acc[r], dup2(a4.x), vv[0]);
                FMA2(acc[r], dup2(a4.y), vv[1]);
                FMA2(acc[r], dup2(a4.z), vv[2]);
                FMA2(acc[r], dup2(a4.w), vv[3]);
            }
        }
    }

    float* ob = out + ((size_t)bh * S_ + i0 + w * 8) * DV_ + l * 2;
    #pragma unroll
    for (int r = 0; r < 8; r++) {
        float2 o = unpack2(acc[r]);
        *(float2*)(ob + (size_t)r * DV_) = o;
    }
}

// ---------------------------------------------------------------------------
extern "C" void kernel_launch(void* const* d_in, const int* in_sizes, int n_in,
                              void* d_out, int out_size)
{
    const float* q    = (const float*)d_in[0];
    const float* k    = (const float*)d_in[1];
    const float* v    = (const float*)d_in[2];
    const int*   mask = (const int*)d_in[3];
    const float* rpr  = (const float*)d_in[4];
    float* out  = (float*)d_out;
    float* attn = out + OUT_ATTN_OFF;

    cudaFuncSetAttribute(k1_qk, cudaFuncAttributeMaxDynamicSharedMemorySize, K1_SMEM);
    cudaFuncSetAttribute(k2_rpr_softmax, cudaFuncAttributeMaxDynamicSharedMemorySize,
                         K2_SMEM_TOTAL);

    {   // K1: attn1 logits into attn region (scratch, rewritten by K2)
        dim3 grid(S_ / 128, S_ / 128, B_ * H_);
        k1_qk<<<grid, 256, K1_SMEM>>>(q, k, attn);
    }
    {   // K2: + positional term, mask, softmax (in place)
        dim3 grid(S_, B_);
        k2_rpr_softmax<<<grid, 256, K2_SMEM_TOTAL>>>(q, rpr, mask, attn);
    }
    {   // K3: output = attn @ v
        dim3 grid(S_ / 64, B_ * H_);
        k3_av<<<grid, 256>>>(attn, v, out);
    }
}